// round 16
// baseline (speedup 1.0000x reference)
#include <cuda_runtime.h>
#include <cuda_bf16.h>
#include <math.h>
#include <stdint.h>

// Problem constants
#define Bn   4
#define Nn   4096
#define Dn   512
#define Hn   8
#define DHn  64
#define Mn   128
#define GTOT (Bn*Nn)          // 16384 rows

// ---------------------------------------------------------------------------
// Device scratch (no cudaMalloc allowed)
// ---------------------------------------------------------------------------
__device__ float g_value[GTOT*Dn];     // [g, h*64+d]
__device__ float g_pos  [GTOT*Dn];
__device__ float g_slope[GTOT*Dn];
__device__ float g_av   [GTOT*Dn];
__device__ float g_kvs  [Bn*Hn*2*Mn*DHn];   // [bh, m(256), d(64)]
__device__ float g_norms[GTOT*Hn];
// fallback q'/k' scratch if harness only compares first output
__device__ float g_qp[(size_t)GTOT*Hn*2*Mn];
__device__ float g_kp[(size_t)GTOT*Hn*2*Mn];

// ---------------------------------------------------------------------------
// bf16x3 helpers: fp32 a = hi + lo (two bf16); D += hi*hi + hi*lo + lo*hi
// ---------------------------------------------------------------------------
__device__ __forceinline__ uint32_t pack_bf16_hl(float f) {
    __nv_bfloat16 h = __float2bfloat16(f);
    float hf = __bfloat162float(h);
    __nv_bfloat16 l = __float2bfloat16(f - hf);
    return ((uint32_t)__bfloat16_as_ushort(h) << 16) |
           (uint32_t)__bfloat16_as_ushort(l);
}
__device__ __forceinline__ uint32_t prmt_hi(uint32_t a, uint32_t b) {
    uint32_t r;
    asm("prmt.b32 %0,%1,%2,0x7632;" : "=r"(r) : "r"(a), "r"(b));
    return r;
}
__device__ __forceinline__ uint32_t prmt_lo(uint32_t a, uint32_t b) {
    uint32_t r;
    asm("prmt.b32 %0,%1,%2,0x5410;" : "=r"(r) : "r"(a), "r"(b));
    return r;
}
__device__ __forceinline__ void mma_bf16(float* d, const uint32_t* a,
                                         const uint32_t* b) {
    asm volatile(
        "mma.sync.aligned.m16n8k16.row.col.f32.bf16.bf16.f32 "
        "{%0,%1,%2,%3}, {%4,%5,%6,%7}, {%8,%9}, {%0,%1,%2,%3};\n"
        : "+f"(d[0]), "+f"(d[1]), "+f"(d[2]), "+f"(d[3])
        : "r"(a[0]), "r"(a[1]), "r"(a[2]), "r"(a[3]),
          "r"(b[0]), "r"(b[1]));
}

#define AS_STRIDE 40    // u32 words per A smem row ([m][k] layout)
#define BS_STRIDE 132   // u32 words per B smem row ([k][n] layout, 128 cols)
#define TCG_BUF  (128*AS_STRIDE + 32*BS_STRIDE)   // 9344 words per stage

// ---------------------------------------------------------------------------
// bf16x3 tensor GEMM: C[16384,512] = A[16384,512] @ B[512,512]
// 256 threads, 8 warps (2x4), warp tile 64m x 32n, double-buffered smem.
// ---------------------------------------------------------------------------
__device__ __forceinline__ void tcg_gload(const float* __restrict__ A,
                                          const float* __restrict__ B,
                                          int row0, int col0, int k0, int tid,
                                          float4* pa, float4* pb)
{
#pragma unroll
    for (int i = 0; i < 4; i++) {
        int m  = (tid >> 3) + i * 32;
        pa[i] = *(const float4*)&A[(size_t)(row0 + m) * 512 + k0 + (tid & 7) * 4];
        int kk = (tid >> 5) + i * 8;
        pb[i] = *(const float4*)&B[(size_t)(k0 + kk) * 512 + col0 + (tid & 31) * 4];
    }
}

__device__ __forceinline__ void tcg_sstore(uint32_t* As, uint32_t* Bs, int tid,
                                           const float4* pa, const float4* pb)
{
#pragma unroll
    for (int i = 0; i < 4; i++) {
        int m = (tid >> 3) + i * 32;
        uint4 u;
        u.x = pack_bf16_hl(pa[i].x); u.y = pack_bf16_hl(pa[i].y);
        u.z = pack_bf16_hl(pa[i].z); u.w = pack_bf16_hl(pa[i].w);
        *(uint4*)&As[m * AS_STRIDE + (tid & 7) * 4] = u;
        int kk = (tid >> 5) + i * 8;
        uint4 v;
        v.x = pack_bf16_hl(pb[i].x); v.y = pack_bf16_hl(pb[i].y);
        v.z = pack_bf16_hl(pb[i].z); v.w = pack_bf16_hl(pb[i].w);
        *(uint4*)&Bs[kk * BS_STRIDE + (tid & 31) * 4] = v;
    }
}

__device__ __forceinline__ void tc_gemm_body(const float* __restrict__ A,
                                             const float* __restrict__ B,
                                             float* __restrict__ C,
                                             uint32_t* sm)
{
    uint32_t* Asb[2] = { sm,                   sm + TCG_BUF };
    uint32_t* Bsb[2] = { sm + 128 * AS_STRIDE, sm + TCG_BUF + 128 * AS_STRIDE };

    const int NC = 512;
    int tid  = threadIdx.x;
    int row0 = blockIdx.x * 128;
    int col0 = blockIdx.y * 128;
    int wid  = tid >> 5, lane = tid & 31;
    int wm = wid >> 2, wn = wid & 3;           // 2 x 4 warp grid
    int group = lane >> 2, cc = lane & 3;

    float acc[4][4][4];
#pragma unroll
    for (int a = 0; a < 4; a++)
#pragma unroll
        for (int b = 0; b < 4; b++)
#pragma unroll
            for (int c = 0; c < 4; c++) acc[a][b][c] = 0.f;

    float4 pa[4], pb[4];
    tcg_gload(A, B, row0, col0, 0, tid, pa, pb);
    tcg_sstore(Asb[0], Bsb[0], tid, pa, pb);
    __syncthreads();

#pragma unroll 1
    for (int ch = 0; ch < 16; ch++) {
        bool more = (ch + 1 < 16);
        if (more) tcg_gload(A, B, row0, col0, (ch + 1) * 32, tid, pa, pb);
        uint32_t* As = Asb[ch & 1];
        uint32_t* Bs = Bsb[ch & 1];

#pragma unroll
        for (int ks = 0; ks < 2; ks++) {
            int kb = ks * 16;
            uint32_t ahi[4][4], alo[4][4];
#pragma unroll
            for (int mt = 0; mt < 4; mt++) {
                int r0  = wm * 64 + mt * 16 + group;
                int kw0 = kb + cc * 2;
                int kw1 = kw0 + 8;
                uint2 w00 = *(uint2*)&As[r0 * AS_STRIDE + kw0];
                uint2 w10 = *(uint2*)&As[(r0 + 8) * AS_STRIDE + kw0];
                uint2 w01 = *(uint2*)&As[r0 * AS_STRIDE + kw1];
                uint2 w11 = *(uint2*)&As[(r0 + 8) * AS_STRIDE + kw1];
                ahi[mt][0] = prmt_hi(w00.x, w00.y); alo[mt][0] = prmt_lo(w00.x, w00.y);
                ahi[mt][1] = prmt_hi(w10.x, w10.y); alo[mt][1] = prmt_lo(w10.x, w10.y);
                ahi[mt][2] = prmt_hi(w01.x, w01.y); alo[mt][2] = prmt_lo(w01.x, w01.y);
                ahi[mt][3] = prmt_hi(w11.x, w11.y); alo[mt][3] = prmt_lo(w11.x, w11.y);
            }
#pragma unroll
            for (int nt = 0; nt < 4; nt++) {
                int col = wn * 32 + nt * 8 + group;
                int kr  = kb + cc * 2;
                uint32_t wk0 = Bs[kr * BS_STRIDE + col];
                uint32_t wk1 = Bs[(kr + 1) * BS_STRIDE + col];
                uint32_t wk8 = Bs[(kr + 8) * BS_STRIDE + col];
                uint32_t wk9 = Bs[(kr + 9) * BS_STRIDE + col];
                uint32_t bhi[2] = { prmt_hi(wk0, wk1), prmt_hi(wk8, wk9) };
                uint32_t blo[2] = { prmt_lo(wk0, wk1), prmt_lo(wk8, wk9) };
#pragma unroll
                for (int mt = 0; mt < 4; mt++) {
                    mma_bf16(acc[mt][nt], ahi[mt], bhi);
                    mma_bf16(acc[mt][nt], ahi[mt], blo);
                    mma_bf16(acc[mt][nt], alo[mt], bhi);
                }
            }
        }
        if (more) tcg_sstore(Asb[(ch + 1) & 1], Bsb[(ch + 1) & 1], tid, pa, pb);
        __syncthreads();
    }

#pragma unroll
    for (int mt = 0; mt < 4; mt++) {
        int r = row0 + wm * 64 + mt * 16 + group;
#pragma unroll
        for (int nt = 0; nt < 4; nt++) {
            int c = col0 + wn * 32 + nt * 8 + cc * 2;
            *(float2*)&C[(size_t)r * NC + c]       = make_float2(acc[mt][nt][0], acc[mt][nt][1]);
            *(float2*)&C[(size_t)(r + 8) * NC + c] = make_float2(acc[mt][nt][2], acc[mt][nt][3]);
        }
    }
}

// 3 projection GEMMs fused over blockIdx.z
__global__ __launch_bounds__(256) void tc_proj(
    const float* __restrict__ A0, const float* __restrict__ A1,
    const float* __restrict__ A2, const float* __restrict__ Bv,
    const float* __restrict__ Bp)
{
    extern __shared__ uint32_t smext[];
    int z = blockIdx.z;
    const float* A = (z == 0) ? A0 : ((z == 1) ? A1 : A2);
    const float* B = (z == 0) ? Bv : Bp;
    float* C = (z == 0) ? g_value : ((z == 1) ? g_pos : g_slope);
    tc_gemm_body(A, B, C, smext);
}

__global__ __launch_bounds__(256) void tc_final(
    const float* __restrict__ Wout, float* __restrict__ out)
{
    extern __shared__ uint32_t smext[];
    tc_gemm_body(g_av, Wout, out, smext);
}

// ---------------------------------------------------------------------------
// Fourier features (fp32 — precision-critical path through sin/cos)
// ---------------------------------------------------------------------------
__global__ __launch_bounds__(256) void fourier_k(
    const float* __restrict__ scale8, const float* __restrict__ off8,
    const float* __restrict__ proj,
    float* __restrict__ qp, float* __restrict__ kp)
{
    extern __shared__ float sm[];
    float* Ps = sm;                   // [64 d][132]  proj transposed
    float* Xq = sm + 64*132;          // [64 d][68]
    float* Xk = Xq + 64*68;           // [64 d][68]

    int tid = threadIdx.x;
    int h   = blockIdx.y;
    int g0  = blockIdx.x * 64;
    float sc  = scale8[h];
    float off = off8[h];
    const float dn    = 0.35355339059327373f;   // 64^-0.25
    const float ratio = 0.08838834764831845f;   // 128^-0.5
    float aq = dn * sc;
    float ak = dn * sc * off;

#pragma unroll
    for (int i = 0; i < 8; i++) {
        int v = tid + i * 256;              // 0..2047 float4
        int m = v >> 4, dq = v & 15;
        float4 p4 = *(const float4*)&proj[m * 64 + dq * 4];
        Ps[(dq*4+0)*132 + m] = p4.x;
        Ps[(dq*4+1)*132 + m] = p4.y;
        Ps[(dq*4+2)*132 + m] = p4.z;
        Ps[(dq*4+3)*132 + m] = p4.w;
    }
#pragma unroll
    for (int i = 0; i < 4; i++) {
        int v  = tid + i * 256;             // 0..1023 float4
        int dq = v & 15, r = v >> 4;
        int base = ((g0 + r) * Hn + h) * 64 + dq * 4;
        float4 pp = *(const float4*)&g_pos[base];
        float4 sp = *(const float4*)&g_slope[base];
        float ss = sp.x*sp.x + sp.y*sp.y + sp.z*sp.z + sp.w*sp.w;
        ss += __shfl_xor_sync(0xffffffffu, ss, 8);
        ss += __shfl_xor_sync(0xffffffffu, ss, 4);
        ss += __shfl_xor_sync(0xffffffffu, ss, 2);
        ss += __shfl_xor_sync(0xffffffffu, ss, 1);
        if (dq == 0) g_norms[(g0 + r) * Hn + h] = sqrtf(ss) * (1.0f/4096.0f);
        Xq[(dq*4+0)*68 + r] = aq*pp.x;  Xk[(dq*4+0)*68 + r] = aq*pp.x + ak*sp.x;
        Xq[(dq*4+1)*68 + r] = aq*pp.y;  Xk[(dq*4+1)*68 + r] = aq*pp.y + ak*sp.y;
        Xq[(dq*4+2)*68 + r] = aq*pp.z;  Xk[(dq*4+2)*68 + r] = aq*pp.z + ak*sp.z;
        Xq[(dq*4+3)*68 + r] = aq*pp.w;  Xk[(dq*4+3)*68 + r] = aq*pp.w + ak*sp.w;
    }
    __syncthreads();

    int tx = tid & 15, ty = tid >> 4;
    int m0 = tx * 8, r0 = ty * 4;
    float accq[4][8], acck[4][8];
#pragma unroll
    for (int i = 0; i < 4; i++)
#pragma unroll
        for (int j = 0; j < 8; j++) { accq[i][j] = 0.f; acck[i][j] = 0.f; }

#pragma unroll 8
    for (int k = 0; k < 64; k++) {
        float4 xq4 = *(float4*)&Xq[k*68 + r0];
        float4 xk4 = *(float4*)&Xk[k*68 + r0];
        float4 p0  = *(float4*)&Ps[k*132 + m0];
        float4 p1  = *(float4*)&Ps[k*132 + m0 + 4];
        float xrq[4] = {xq4.x, xq4.y, xq4.z, xq4.w};
        float xrk[4] = {xk4.x, xk4.y, xk4.z, xk4.w};
        float pr[8]  = {p0.x,p0.y,p0.z,p0.w,p1.x,p1.y,p1.z,p1.w};
#pragma unroll
        for (int i = 0; i < 4; i++)
#pragma unroll
            for (int j = 0; j < 8; j++) {
                accq[i][j] += xrq[i] * pr[j];
                acck[i][j] += xrk[i] * pr[j];
            }
    }

#pragma unroll
    for (int i = 0; i < 4; i++) {
        int ob = ((g0 + r0 + i) * Hn + h) * 256 + m0;
#pragma unroll
        for (int j = 0; j < 8; j++) {
            float sq, cq, sk, ck;
            sincosf(accq[i][j], &sq, &cq);
            sincosf(acck[i][j], &sk, &ck);
            qp[ob + j]       = ratio * sq;
            qp[ob + 128 + j] = ratio * cq;
            kp[ob + j]       = ratio * sk;
            kp[ob + 128 + j] = ratio * ck;
        }
    }
}

// ---------------------------------------------------------------------------
// kvs (tensor): kvs[bh,m,d] += sum_n k'[n,h,m] * value[n,h,d]
// 256 threads / 8 warps (warp = 32 m rows), double-buffered, split-N atomics.
// ---------------------------------------------------------------------------
__global__ void zero_kvs_k()
{
    int i = blockIdx.x * blockDim.x + threadIdx.x;
    if (i < Bn*Hn*2*Mn*DHn) g_kvs[i] = 0.f;
}

#define KT_STRIDE 260   // [n][m] packed layout
#define KVS_BUF  (32*KT_STRIDE + 32*68)   // 10496 words per stage

__device__ __forceinline__ void kvs_gload(const float* __restrict__ kp,
                                          int nbase, int h, int tid,
                                          float4* pk, float4* pv)
{
#pragma unroll
    for (int i = 0; i < 8; i++) {
        int v = tid + i * 256;            // 0..2047
        int nrow = v >> 6, mq = v & 63;
        pk[i] = *(const float4*)&kp[((size_t)(nbase + nrow) * Hn + h) * 256 + mq * 4];
    }
#pragma unroll
    for (int i = 0; i < 2; i++) {
        int v = tid + i * 256;            // 0..511
        int nrow = v >> 4, dq = v & 15;
        pv[i] = *(const float4*)&g_value[((size_t)(nbase + nrow) * Hn + h) * 64 + dq * 4];
    }
}

__device__ __forceinline__ void kvs_sstore(uint32_t* Ks, uint32_t* Vs, int tid,
                                           const float4* pk, const float4* pv)
{
#pragma unroll
    for (int i = 0; i < 8; i++) {
        int v = tid + i * 256;
        int nrow = v >> 6, mq = v & 63;
        uint4 u;
        u.x = pack_bf16_hl(pk[i].x); u.y = pack_bf16_hl(pk[i].y);
        u.z = pack_bf16_hl(pk[i].z); u.w = pack_bf16_hl(pk[i].w);
        *(uint4*)&Ks[nrow * KT_STRIDE + mq * 4] = u;
    }
#pragma unroll
    for (int i = 0; i < 2; i++) {
        int v = tid + i * 256;
        int nrow = v >> 4, dq = v & 15;
        uint4 u;
        u.x = pack_bf16_hl(pv[i].x); u.y = pack_bf16_hl(pv[i].y);
        u.z = pack_bf16_hl(pv[i].z); u.w = pack_bf16_hl(pv[i].w);
        *(uint4*)&Vs[nrow * 68 + dq * 4] = u;
    }
}

__global__ __launch_bounds__(256) void kvs_tc(const float* __restrict__ kp)
{
    extern __shared__ uint32_t smext[];
    uint32_t* Ksb[2] = { smext,                  smext + KVS_BUF };
    uint32_t* Vsb[2] = { smext + 32 * KT_STRIDE, smext + KVS_BUF + 32 * KT_STRIDE };

    int bh = blockIdx.x, b = bh >> 3, h = bh & 7;
    int nbase = b * Nn + blockIdx.y * 256;
    int tid = threadIdx.x;
    int wid = tid >> 5, lane = tid & 31;
    int group = lane >> 2, cc = lane & 3;
    int m0 = wid * 32;

    float acc[2][8][4];
#pragma unroll
    for (int a = 0; a < 2; a++)
#pragma unroll
        for (int c = 0; c < 8; c++)
#pragma unroll
            for (int e = 0; e < 4; e++) acc[a][c][e] = 0.f;

    float4 pk[8], pv[2];
    kvs_gload(kp, nbase, h, tid, pk, pv);
    kvs_sstore(Ksb[0], Vsb[0], tid, pk, pv);
    __syncthreads();

#pragma unroll 1
    for (int ch = 0; ch < 8; ch++) {
        bool more = (ch + 1 < 8);
        if (more) kvs_gload(kp, nbase + (ch + 1) * 32, h, tid, pk, pv);
        uint32_t* Ks = Ksb[ch & 1];
        uint32_t* Vs = Vsb[ch & 1];

#pragma unroll
        for (int ks = 0; ks < 32; ks += 16) {
            int k0 = ks + cc * 2;
            uint32_t ahi[2][4], alo[2][4];
#pragma unroll
            for (int mt = 0; mt < 2; mt++) {
                int mr = m0 + mt * 16 + group;
                uint32_t e00 = Ks[k0 * KT_STRIDE + mr];
                uint32_t e01 = Ks[(k0 + 1) * KT_STRIDE + mr];
                uint32_t e10 = Ks[k0 * KT_STRIDE + mr + 8];
                uint32_t e11 = Ks[(k0 + 1) * KT_STRIDE + mr + 8];
                uint32_t e02 = Ks[(k0 + 8) * KT_STRIDE + mr];
                uint32_t e03 = Ks[(k0 + 9) * KT_STRIDE + mr];
                uint32_t e12 = Ks[(k0 + 8) * KT_STRIDE + mr + 8];
                uint32_t e13 = Ks[(k0 + 9) * KT_STRIDE + mr + 8];
                ahi[mt][0] = prmt_hi(e00, e01); alo[mt][0] = prmt_lo(e00, e01);
                ahi[mt][1] = prmt_hi(e10, e11); alo[mt][1] = prmt_lo(e10, e11);
                ahi[mt][2] = prmt_hi(e02, e03); alo[mt][2] = prmt_lo(e02, e03);
                ahi[mt][3] = prmt_hi(e12, e13); alo[mt][3] = prmt_lo(e12, e13);
            }
#pragma unroll
            for (int nt = 0; nt < 8; nt++) {
                int col = nt * 8 + group;
                uint32_t wk0 = Vs[k0 * 68 + col];
                uint32_t wk1 = Vs[(k0 + 1) * 68 + col];
                uint32_t wk8 = Vs[(k0 + 8) * 68 + col];
                uint32_t wk9 = Vs[(k0 + 9) * 68 + col];
                uint32_t bhi[2] = { prmt_hi(wk0, wk1), prmt_hi(wk8, wk9) };
                uint32_t blo[2] = { prmt_lo(wk0, wk1), prmt_lo(wk8, wk9) };
#pragma unroll
                for (int mt = 0; mt < 2; mt++) {
                    mma_bf16(acc[mt][nt], ahi[mt], bhi);
                    mma_bf16(acc[mt][nt], ahi[mt], blo);
                    mma_bf16(acc[mt][nt], alo[mt], bhi);
                }
            }
        }
        if (more) kvs_sstore(Ksb[(ch + 1) & 1], Vsb[(ch + 1) & 1], tid, pk, pv);
        __syncthreads();
    }

#pragma unroll
    for (int mt = 0; mt < 2; mt++) {
        int mr = m0 + mt * 16 + group;
#pragma unroll
        for (int nt = 0; nt < 8; nt++) {
            int col = nt * 8 + cc * 2;
            atomicAdd(&g_kvs[(bh * 256 + mr) * 64 + col],         acc[mt][nt][0]);
            atomicAdd(&g_kvs[(bh * 256 + mr) * 64 + col + 1],     acc[mt][nt][1]);
            atomicAdd(&g_kvs[(bh * 256 + mr + 8) * 64 + col],     acc[mt][nt][2]);
            atomicAdd(&g_kvs[(bh * 256 + mr + 8) * 64 + col + 1], acc[mt][nt][3]);
        }
    }
}

// ---------------------------------------------------------------------------
// av (tensor): av[g, h*64+d] = norms[g,h] * sum_m q'[g,h,m] * kvs[bh,m,d]
// 256 threads / 8 warps (4x2), warp tile 32g x 32d, double-buffered.
// ---------------------------------------------------------------------------
#define AV_BUF (128*AS_STRIDE + 32*68)   // 7296 words per stage

__device__ __forceinline__ void av_gload(const float* __restrict__ qp,
                                         const float* __restrict__ kvsrc,
                                         int g0, int h, int mc, int tid,
                                         float4* pa, float4* pb)
{
#pragma unroll
    for (int i = 0; i < 4; i++) {
        int m = (tid >> 3) + i * 32;
        pa[i] = *(const float4*)&qp[((size_t)(g0 + m) * Hn + h) * 256 + mc + (tid & 7) * 4];
    }
#pragma unroll
    for (int i = 0; i < 2; i++) {
        int v = tid + i * 256;
        int kk = v >> 4, dq = v & 15;
        pb[i] = *(const float4*)&kvsrc[(size_t)(mc + kk) * 64 + dq * 4];
    }
}

__device__ __forceinline__ void av_sstore(uint32_t* As, uint32_t* Bs, int tid,
                                          const float4* pa, const float4* pb)
{
#pragma unroll
    for (int i = 0; i < 4; i++) {
        int m = (tid >> 3) + i * 32;
        uint4 u;
        u.x = pack_bf16_hl(pa[i].x); u.y = pack_bf16_hl(pa[i].y);
        u.z = pack_bf16_hl(pa[i].z); u.w = pack_bf16_hl(pa[i].w);
        *(uint4*)&As[m * AS_STRIDE + (tid & 7) * 4] = u;
    }
#pragma unroll
    for (int i = 0; i < 2; i++) {
        int v = tid + i * 256;
        int kk = v >> 4, dq = v & 15;
        uint4 u;
        u.x = pack_bf16_hl(pb[i].x); u.y = pack_bf16_hl(pb[i].y);
        u.z = pack_bf16_hl(pb[i].z); u.w = pack_bf16_hl(pb[i].w);
        *(uint4*)&Bs[kk * 68 + dq * 4] = u;
    }
}

__global__ __launch_bounds__(256, 2) void av_tc(const float* __restrict__ qp)
{
    extern __shared__ uint32_t smext[];
    uint32_t* Asb[2] = { smext,                   smext + AV_BUF };
    uint32_t* Bsb[2] = { smext + 128 * AS_STRIDE, smext + AV_BUF + 128 * AS_STRIDE };

    int h  = blockIdx.y;
    int g0 = blockIdx.x * 128;
    int bh = (g0 >> 12) * Hn + h;
    const float* kvsrc = &g_kvs[(size_t)bh * 256 * 64];
    int tid = threadIdx.x;
    int wid = tid >> 5, lane = tid & 31;
    int wm = wid >> 1, wn = wid & 1;          // 4 x 2
    int group = lane >> 2, cc = lane & 3;

    float acc[2][4][4];
#pragma unroll
    for (int a = 0; a < 2; a++)
#pragma unroll
        for (int c = 0; c < 4; c++)
#pragma unroll
            for (int e = 0; e < 4; e++) acc[a][c][e] = 0.f;

    float4 pa[4], pb[2];
    av_gload(qp, kvsrc, g0, h, 0, tid, pa, pb);
    av_sstore(Asb[0], Bsb[0], tid, pa, pb);
    __syncthreads();

#pragma unroll 1
    for (int ch = 0; ch < 8; ch++) {
        bool more = (ch + 1 < 8);
        if (more) av_gload(qp, kvsrc, g0, h, (ch + 1) * 32, tid, pa, pb);
        uint32_t* As = Asb[ch & 1];
        uint32_t* Bs = Bsb[ch & 1];

#pragma unroll
        for (int ks = 0; ks < 32; ks += 16) {
            uint32_t ahi[2][4], alo[2][4];
#pragma unroll
            for (int mt = 0; mt < 2; mt++) {
                int r0  = wm * 32 + mt * 16 + group;
                int kw0 = ks + cc * 2;
                int kw1 = kw0 + 8;
                uint2 w00 = *(uint2*)&As[r0 * AS_STRIDE + kw0];
                uint2 w10 = *(uint2*)&As[(r0 + 8) * AS_STRIDE + kw0];
                uint2 w01 = *(uint2*)&As[r0 * AS_STRIDE + kw1];
                uint2 w11 = *(uint2*)&As[(r0 + 8) * AS_STRIDE + kw1];
                ahi[mt][0] = prmt_hi(w00.x, w00.y); alo[mt][0] = prmt_lo(w00.x, w00.y);
                ahi[mt][1] = prmt_hi(w10.x, w10.y); alo[mt][1] = prmt_lo(w10.x, w10.y);
                ahi[mt][2] = prmt_hi(w01.x, w01.y); alo[mt][2] = prmt_lo(w01.x, w01.y);
                ahi[mt][3] = prmt_hi(w11.x, w11.y); alo[mt][3] = prmt_lo(w11.x, w11.y);
            }
#pragma unroll
            for (int nt = 0; nt < 4; nt++) {
                int col = wn * 32 + nt * 8 + group;
                int kr  = ks + cc * 2;
                uint32_t wk0 = Bs[kr * 68 + col];
                uint32_t wk1 = Bs[(kr + 1) * 68 + col];
                uint32_t wk8 = Bs[(kr + 8) * 68 + col];
                uint32_t wk9 = Bs[(kr + 9) * 68 + col];
                uint32_t bhi[2] = { prmt_hi(wk0, wk1), prmt_hi(wk8, wk9) };
                uint32_t blo[2] = { prmt_lo(wk0, wk1), prmt_lo(wk8, wk9) };
#pragma unroll
                for (int mt = 0; mt < 2; mt++) {
                    mma_bf16(acc[mt][nt], ahi[mt], bhi);
                    mma_bf16(acc[mt][nt], ahi[mt], blo);
                    mma_bf16(acc[mt][nt], alo[mt], bhi);
                }
            }
        }
        if (more) av_sstore(Asb[(ch + 1) & 1], Bsb[(ch + 1) & 1], tid, pa, pb);
        __syncthreads();
    }

#pragma unroll
    for (int mt = 0; mt < 2; mt++) {
        int g  = g0 + wm * 32 + mt * 16 + group;
        float nr0 = g_norms[(size_t)g * Hn + h];
        float nr1 = g_norms[(size_t)(g + 8) * Hn + h];
#pragma unroll
        for (int nt = 0; nt < 4; nt++) {
            int c = h * 64 + wn * 32 + nt * 8 + cc * 2;
            *(float2*)&g_av[(size_t)g * Dn + c]
                = make_float2(nr0 * acc[mt][nt][0], nr0 * acc[mt][nt][1]);
            *(float2*)&g_av[(size_t)(g + 8) * Dn + c]
                = make_float2(nr1 * acc[mt][nt][2], nr1 * acc[mt][nt][3]);
        }
    }
}

// ---------------------------------------------------------------------------
// Launch
// ---------------------------------------------------------------------------
extern "C" void kernel_launch(void* const* d_in, const int* in_sizes, int n_in,
                              void* d_out, int out_size)
{
    const float* src   = (const float*)d_in[0];   // source_input [B,N,D]
    const float* posf  = (const float*)d_in[1];   // pos_ft
    const float* slope = (const float*)d_in[2];   // pos_ft_slopes
    const float* Wv    = (const float*)d_in[3];   // value_weight [D,H,DH]
    const float* Wp    = (const float*)d_in[4];   // pos_ft_weight
    const float* scale = (const float*)d_in[5];   // [H]
    const float* offs  = (const float*)d_in[6];   // [H]
    const float* Wout  = (const float*)d_in[7];   // [H*DH, D]
    const float* proj  = (const float*)d_in[8];   // [M, DH]
    float* out = (float*)d_out;

    // Output layout: [out (B*N*D) | q_prime (B*N*H*2M) | k_prime (B*N*H*2M)]
    const long QOFF = (long)GTOT * Dn;                 //  8,388,608
    const long KOFF = QOFF + (long)GTOT * Hn * 2 * Mn; // 41,943,040
    const long TOT  = KOFF + (long)GTOT * Hn * 2 * Mn; // 75,497,472

    float *qp, *kp;
    if ((long)out_size >= TOT) {
        qp = out + QOFF;
        kp = out + KOFF;
    } else {
        cudaGetSymbolAddress((void**)&qp, g_qp);
        cudaGetSymbolAddress((void**)&kp, g_kp);
    }

    size_t fsmem   = (size_t)(64*132 + 2*64*68) * sizeof(float);  // 69632 B
    size_t gemsmem = (size_t)(2 * TCG_BUF) * sizeof(uint32_t);    // 74752 B
    size_t kvsmem  = (size_t)(2 * KVS_BUF) * sizeof(uint32_t);    // 83968 B
    size_t avsmem  = (size_t)(2 * AV_BUF)  * sizeof(uint32_t);    // 58368 B
    cudaFuncSetAttribute(fourier_k, cudaFuncAttributeMaxDynamicSharedMemorySize,
                         (int)fsmem);
    cudaFuncSetAttribute(tc_proj,  cudaFuncAttributeMaxDynamicSharedMemorySize,
                         (int)gemsmem);
    cudaFuncSetAttribute(tc_final, cudaFuncAttributeMaxDynamicSharedMemorySize,
                         (int)gemsmem);
    cudaFuncSetAttribute(kvs_tc,   cudaFuncAttributeMaxDynamicSharedMemorySize,
                         (int)kvsmem);
    cudaFuncSetAttribute(av_tc,    cudaFuncAttributeMaxDynamicSharedMemorySize,
                         (int)avsmem);

    zero_kvs_k<<<2048, 256>>>();
    tc_proj<<<dim3(128, 4, 3), 256, gemsmem>>>(src, posf, slope, Wv, Wp);
    fourier_k<<<dim3(256, 8), 256, fsmem>>>(scale, offs, proj, qp, kp);
    kvs_tc<<<dim3(32, 16), 256, kvsmem>>>(kp);
    av_tc<<<dim3(128, 8), 256, avsmem>>>(qp);
    tc_final<<<dim3(128, 4), 256, gemsmem>>>(Wout, out);
}

// round 17
// speedup vs baseline: 1.1343x; 1.1343x over previous
#include <cuda_runtime.h>
#include <cuda_bf16.h>
#include <math.h>
#include <stdint.h>

// Problem constants
#define Bn   4
#define Nn   4096
#define Dn   512
#define Hn   8
#define DHn  64
#define Mn   128
#define GTOT (Bn*Nn)          // 16384 rows

// ---------------------------------------------------------------------------
// Device scratch (no cudaMalloc allowed)
// ---------------------------------------------------------------------------
__device__ float g_value[GTOT*Dn];     // [g, h*64+d]
__device__ float g_pos  [GTOT*Dn];
__device__ float g_slope[GTOT*Dn];
__device__ float g_av   [GTOT*Dn];
__device__ float g_kvs  [Bn*Hn*2*Mn*DHn];   // [bh, m(256), d(64)]
__device__ float g_norms[GTOT*Hn];
// fallback q'/k' scratch if harness only compares first output
__device__ float g_qp[(size_t)GTOT*Hn*2*Mn];
__device__ float g_kp[(size_t)GTOT*Hn*2*Mn];

// ---------------------------------------------------------------------------
// bf16x3 helpers: fp32 a = hi + lo (two bf16); D += hi*hi + hi*lo + lo*hi
// ---------------------------------------------------------------------------
__device__ __forceinline__ uint32_t pack_bf16_hl(float f) {
    __nv_bfloat16 h = __float2bfloat16(f);
    float hf = __bfloat162float(h);
    __nv_bfloat16 l = __float2bfloat16(f - hf);
    return ((uint32_t)__bfloat16_as_ushort(h) << 16) |
           (uint32_t)__bfloat16_as_ushort(l);
}
__device__ __forceinline__ uint32_t prmt_hi(uint32_t a, uint32_t b) {
    uint32_t r;
    asm("prmt.b32 %0,%1,%2,0x7632;" : "=r"(r) : "r"(a), "r"(b));
    return r;
}
__device__ __forceinline__ uint32_t prmt_lo(uint32_t a, uint32_t b) {
    uint32_t r;
    asm("prmt.b32 %0,%1,%2,0x5410;" : "=r"(r) : "r"(a), "r"(b));
    return r;
}
__device__ __forceinline__ void mma_bf16(float* d, const uint32_t* a,
                                         const uint32_t* b) {
    asm volatile(
        "mma.sync.aligned.m16n8k16.row.col.f32.bf16.bf16.f32 "
        "{%0,%1,%2,%3}, {%4,%5,%6,%7}, {%8,%9}, {%0,%1,%2,%3};\n"
        : "+f"(d[0]), "+f"(d[1]), "+f"(d[2]), "+f"(d[3])
        : "r"(a[0]), "r"(a[1]), "r"(a[2]), "r"(a[3]),
          "r"(b[0]), "r"(b[1]));
}

#define AS_STRIDE 40    // u32 words per A smem row (conflict-free for frag loads)
#define BS_STRIDE 132   // u32 words per B smem row

// ---------------------------------------------------------------------------
// bf16x3 tensor GEMM: C[16384,512] = A[16384,512] @ B[512,512]
// 256 threads, 8 warps (2x4), warp tile 64m x 32n, register prefetch.
// ---------------------------------------------------------------------------
__device__ __forceinline__ void tcg_gload(const float* __restrict__ A,
                                          const float* __restrict__ B,
                                          int row0, int col0, int k0, int tid,
                                          float4* pa, float4* pb)
{
#pragma unroll
    for (int i = 0; i < 4; i++) {
        int m  = (tid >> 3) + i * 32;
        pa[i] = *(const float4*)&A[(size_t)(row0 + m) * 512 + k0 + (tid & 7) * 4];
        int kk = (tid >> 5) + i * 8;
        pb[i] = *(const float4*)&B[(size_t)(k0 + kk) * 512 + col0 + (tid & 31) * 4];
    }
}

__device__ __forceinline__ void tcg_sstore(uint32_t* As, uint32_t* Bs, int tid,
                                           const float4* pa, const float4* pb)
{
#pragma unroll
    for (int i = 0; i < 4; i++) {
        int m = (tid >> 3) + i * 32;
        uint4 u;
        u.x = pack_bf16_hl(pa[i].x); u.y = pack_bf16_hl(pa[i].y);
        u.z = pack_bf16_hl(pa[i].z); u.w = pack_bf16_hl(pa[i].w);
        *(uint4*)&As[m * AS_STRIDE + (tid & 7) * 4] = u;
        int kk = (tid >> 5) + i * 8;
        uint4 v;
        v.x = pack_bf16_hl(pb[i].x); v.y = pack_bf16_hl(pb[i].y);
        v.z = pack_bf16_hl(pb[i].z); v.w = pack_bf16_hl(pb[i].w);
        *(uint4*)&Bs[kk * BS_STRIDE + (tid & 31) * 4] = v;
    }
}

__device__ __forceinline__ void tc_gemm_body(const float* __restrict__ A,
                                             const float* __restrict__ B,
                                             float* __restrict__ C)
{
    __shared__ uint32_t As[128 * AS_STRIDE];   // [m][k] packed (hi<<16|lo)
    __shared__ uint32_t Bs[32 * BS_STRIDE];    // [k][n] packed

    const int K = 512, NC = 512;
    int tid  = threadIdx.x;
    int row0 = blockIdx.x * 128;
    int col0 = blockIdx.y * 128;
    int wid  = tid >> 5, lane = tid & 31;
    int wm = wid >> 2, wn = wid & 3;           // 2 x 4 warp grid
    int group = lane >> 2, cc = lane & 3;

    float acc[4][4][4];
#pragma unroll
    for (int a = 0; a < 4; a++)
#pragma unroll
        for (int b = 0; b < 4; b++)
#pragma unroll
            for (int c = 0; c < 4; c++) acc[a][b][c] = 0.f;

    float4 pa[4], pb[4];
    tcg_gload(A, B, row0, col0, 0, tid, pa, pb);
    tcg_sstore(As, Bs, tid, pa, pb);
    __syncthreads();

    for (int k0 = 0; k0 < K; k0 += 32) {
        bool more = (k0 + 32 < K);
        if (more) tcg_gload(A, B, row0, col0, k0 + 32, tid, pa, pb);

#pragma unroll
        for (int ks = 0; ks < 2; ks++) {
            int kb = ks * 16;
            uint32_t ahi[4][4], alo[4][4];
#pragma unroll
            for (int mt = 0; mt < 4; mt++) {
                int r0  = wm * 64 + mt * 16 + group;
                int kw0 = kb + cc * 2;
                int kw1 = kw0 + 8;
                uint2 w00 = *(uint2*)&As[r0 * AS_STRIDE + kw0];
                uint2 w10 = *(uint2*)&As[(r0 + 8) * AS_STRIDE + kw0];
                uint2 w01 = *(uint2*)&As[r0 * AS_STRIDE + kw1];
                uint2 w11 = *(uint2*)&As[(r0 + 8) * AS_STRIDE + kw1];
                ahi[mt][0] = prmt_hi(w00.x, w00.y); alo[mt][0] = prmt_lo(w00.x, w00.y);
                ahi[mt][1] = prmt_hi(w10.x, w10.y); alo[mt][1] = prmt_lo(w10.x, w10.y);
                ahi[mt][2] = prmt_hi(w01.x, w01.y); alo[mt][2] = prmt_lo(w01.x, w01.y);
                ahi[mt][3] = prmt_hi(w11.x, w11.y); alo[mt][3] = prmt_lo(w11.x, w11.y);
            }
#pragma unroll
            for (int nt = 0; nt < 4; nt++) {
                int col = wn * 32 + nt * 8 + group;
                int kr  = kb + cc * 2;
                uint32_t wk0 = Bs[kr * BS_STRIDE + col];
                uint32_t wk1 = Bs[(kr + 1) * BS_STRIDE + col];
                uint32_t wk8 = Bs[(kr + 8) * BS_STRIDE + col];
                uint32_t wk9 = Bs[(kr + 9) * BS_STRIDE + col];
                uint32_t bhi[2] = { prmt_hi(wk0, wk1), prmt_hi(wk8, wk9) };
                uint32_t blo[2] = { prmt_lo(wk0, wk1), prmt_lo(wk8, wk9) };
#pragma unroll
                for (int mt = 0; mt < 4; mt++) {
                    mma_bf16(acc[mt][nt], ahi[mt], bhi);
                    mma_bf16(acc[mt][nt], ahi[mt], blo);
                    mma_bf16(acc[mt][nt], alo[mt], bhi);
                }
            }
        }
        __syncthreads();
        if (more) {
            tcg_sstore(As, Bs, tid, pa, pb);
            __syncthreads();
        }
    }

#pragma unroll
    for (int mt = 0; mt < 4; mt++) {
        int r = row0 + wm * 64 + mt * 16 + group;
#pragma unroll
        for (int nt = 0; nt < 4; nt++) {
            int c = col0 + wn * 32 + nt * 8 + cc * 2;
            *(float2*)&C[(size_t)r * NC + c]       = make_float2(acc[mt][nt][0], acc[mt][nt][1]);
            *(float2*)&C[(size_t)(r + 8) * NC + c] = make_float2(acc[mt][nt][2], acc[mt][nt][3]);
        }
    }
}

// 3 projection GEMMs fused over blockIdx.z
__global__ __launch_bounds__(256) void tc_proj(
    const float* __restrict__ A0, const float* __restrict__ A1,
    const float* __restrict__ A2, const float* __restrict__ Bv,
    const float* __restrict__ Bp)
{
    int z = blockIdx.z;
    const float* A = (z == 0) ? A0 : ((z == 1) ? A1 : A2);
    const float* B = (z == 0) ? Bv : Bp;
    float* C = (z == 0) ? g_value : ((z == 1) ? g_pos : g_slope);
    tc_gemm_body(A, B, C);
}

__global__ __launch_bounds__(256) void tc_final(
    const float* __restrict__ Wout, float* __restrict__ out)
{
    tc_gemm_body(g_av, Wout, out);
}

// ---------------------------------------------------------------------------
// Fourier features (fp32 — precision-critical path through sin/cos)
// ---------------------------------------------------------------------------
__global__ __launch_bounds__(256) void fourier_k(
    const float* __restrict__ scale8, const float* __restrict__ off8,
    const float* __restrict__ proj,
    float* __restrict__ qp, float* __restrict__ kp)
{
    extern __shared__ float sm[];
    float* Ps = sm;                   // [64 d][132]  proj transposed
    float* Xq = sm + 64*132;          // [64 d][68]
    float* Xk = Xq + 64*68;           // [64 d][68]

    int tid = threadIdx.x;
    int h   = blockIdx.y;
    int g0  = blockIdx.x * 64;
    float sc  = scale8[h];
    float off = off8[h];
    const float dn    = 0.35355339059327373f;   // 64^-0.25
    const float ratio = 0.08838834764831845f;   // 128^-0.5
    float aq = dn * sc;
    float ak = dn * sc * off;

#pragma unroll
    for (int i = 0; i < 8; i++) {
        int v = tid + i * 256;              // 0..2047 float4
        int m = v >> 4, dq = v & 15;
        float4 p4 = *(const float4*)&proj[m * 64 + dq * 4];
        Ps[(dq*4+0)*132 + m] = p4.x;
        Ps[(dq*4+1)*132 + m] = p4.y;
        Ps[(dq*4+2)*132 + m] = p4.z;
        Ps[(dq*4+3)*132 + m] = p4.w;
    }
#pragma unroll
    for (int i = 0; i < 4; i++) {
        int v  = tid + i * 256;             // 0..1023 float4
        int dq = v & 15, r = v >> 4;
        int base = ((g0 + r) * Hn + h) * 64 + dq * 4;
        float4 pp = *(const float4*)&g_pos[base];
        float4 sp = *(const float4*)&g_slope[base];
        float ss = sp.x*sp.x + sp.y*sp.y + sp.z*sp.z + sp.w*sp.w;
        ss += __shfl_xor_sync(0xffffffffu, ss, 8);
        ss += __shfl_xor_sync(0xffffffffu, ss, 4);
        ss += __shfl_xor_sync(0xffffffffu, ss, 2);
        ss += __shfl_xor_sync(0xffffffffu, ss, 1);
        if (dq == 0) g_norms[(g0 + r) * Hn + h] = sqrtf(ss) * (1.0f/4096.0f);
        Xq[(dq*4+0)*68 + r] = aq*pp.x;  Xk[(dq*4+0)*68 + r] = aq*pp.x + ak*sp.x;
        Xq[(dq*4+1)*68 + r] = aq*pp.y;  Xk[(dq*4+1)*68 + r] = aq*pp.y + ak*sp.y;
        Xq[(dq*4+2)*68 + r] = aq*pp.z;  Xk[(dq*4+2)*68 + r] = aq*pp.z + ak*sp.z;
        Xq[(dq*4+3)*68 + r] = aq*pp.w;  Xk[(dq*4+3)*68 + r] = aq*pp.w + ak*sp.w;
    }
    __syncthreads();

    int tx = tid & 15, ty = tid >> 4;
    int m0 = tx * 8, r0 = ty * 4;
    float accq[4][8], acck[4][8];
#pragma unroll
    for (int i = 0; i < 4; i++)
#pragma unroll
        for (int j = 0; j < 8; j++) { accq[i][j] = 0.f; acck[i][j] = 0.f; }

#pragma unroll 8
    for (int k = 0; k < 64; k++) {
        float4 xq4 = *(float4*)&Xq[k*68 + r0];
        float4 xk4 = *(float4*)&Xk[k*68 + r0];
        float4 p0  = *(float4*)&Ps[k*132 + m0];
        float4 p1  = *(float4*)&Ps[k*132 + m0 + 4];
        float xrq[4] = {xq4.x, xq4.y, xq4.z, xq4.w};
        float xrk[4] = {xk4.x, xk4.y, xk4.z, xk4.w};
        float pr[8]  = {p0.x,p0.y,p0.z,p0.w,p1.x,p1.y,p1.z,p1.w};
#pragma unroll
        for (int i = 0; i < 4; i++)
#pragma unroll
            for (int j = 0; j < 8; j++) {
                accq[i][j] += xrq[i] * pr[j];
                acck[i][j] += xrk[i] * pr[j];
            }
    }

#pragma unroll
    for (int i = 0; i < 4; i++) {
        int ob = ((g0 + r0 + i) * Hn + h) * 256 + m0;
#pragma unroll
        for (int j = 0; j < 8; j++) {
            float sq, cq, sk, ck;
            sincosf(accq[i][j], &sq, &cq);
            sincosf(acck[i][j], &sk, &ck);
            qp[ob + j]       = ratio * sq;
            qp[ob + 128 + j] = ratio * cq;
            kp[ob + j]       = ratio * sk;
            kp[ob + 128 + j] = ratio * ck;
        }
    }
}

// ---------------------------------------------------------------------------
// kvs (tensor): kvs[bh,m,d] += sum_n k'[n,h,m] * value[n,h,d]
// 256 threads / 8 warps (warp = 32 m rows), 2 CTAs/SM, split-N atomics.
// ---------------------------------------------------------------------------
__global__ void zero_kvs_k()
{
    int i = blockIdx.x * blockDim.x + threadIdx.x;
    if (i < Bn*Hn*2*Mn*DHn) g_kvs[i] = 0.f;
}

#define KT_STRIDE 260   // [n][m] packed layout: conflict-free frag loads
__global__ __launch_bounds__(256, 2) void kvs_tc(const float* __restrict__ kp)
{
    __shared__ uint32_t Ks[32 * KT_STRIDE];   // [n(32)][m(256)] packed
    __shared__ uint32_t Vs[32 * 68];          // [n(32)][d(64)] packed

    int bh = blockIdx.x, b = bh >> 3, h = bh & 7;
    int nbase = b * Nn + blockIdx.y * 256;
    int tid = threadIdx.x;
    int wid = tid >> 5, lane = tid & 31;
    int group = lane >> 2, cc = lane & 3;
    int m0 = wid * 32;

    float acc[2][8][4];
#pragma unroll
    for (int a = 0; a < 2; a++)
#pragma unroll
        for (int c = 0; c < 8; c++)
#pragma unroll
            for (int e = 0; e < 4; e++) acc[a][c][e] = 0.f;

    for (int nc = 0; nc < 256; nc += 32) {
        // K' chunk: 32 n x 256 m, transposed store [n][m]
#pragma unroll
        for (int i = 0; i < 8; i++) {
            int v = tid + i * 256;            // 0..2047
            int nrow = v >> 6, mq = v & 63;
            float4 f = *(const float4*)&kp[((size_t)(nbase + nc + nrow) * Hn + h) * 256 + mq * 4];
            uint4 u;
            u.x = pack_bf16_hl(f.x); u.y = pack_bf16_hl(f.y);
            u.z = pack_bf16_hl(f.z); u.w = pack_bf16_hl(f.w);
            *(uint4*)&Ks[nrow * KT_STRIDE + mq * 4] = u;
        }
        // V chunk: 32 n x 64 d
#pragma unroll
        for (int i = 0; i < 2; i++) {
            int v = tid + i * 256;            // 0..511
            int nrow = v >> 4, dq = v & 15;
            float4 f = *(const float4*)&g_value[((size_t)(nbase + nc + nrow) * Hn + h) * 64 + dq * 4];
            uint4 u;
            u.x = pack_bf16_hl(f.x); u.y = pack_bf16_hl(f.y);
            u.z = pack_bf16_hl(f.z); u.w = pack_bf16_hl(f.w);
            *(uint4*)&Vs[nrow * 68 + dq * 4] = u;
        }
        __syncthreads();

#pragma unroll
        for (int ks = 0; ks < 32; ks += 16) {
            int k0 = ks + cc * 2;
            uint32_t ahi[2][4], alo[2][4];
#pragma unroll
            for (int mt = 0; mt < 2; mt++) {
                int mr = m0 + mt * 16 + group;
                uint32_t e00 = Ks[k0 * KT_STRIDE + mr];
                uint32_t e01 = Ks[(k0 + 1) * KT_STRIDE + mr];
                uint32_t e10 = Ks[k0 * KT_STRIDE + mr + 8];
                uint32_t e11 = Ks[(k0 + 1) * KT_STRIDE + mr + 8];
                uint32_t e02 = Ks[(k0 + 8) * KT_STRIDE + mr];
                uint32_t e03 = Ks[(k0 + 9) * KT_STRIDE + mr];
                uint32_t e12 = Ks[(k0 + 8) * KT_STRIDE + mr + 8];
                uint32_t e13 = Ks[(k0 + 9) * KT_STRIDE + mr + 8];
                ahi[mt][0] = prmt_hi(e00, e01); alo[mt][0] = prmt_lo(e00, e01);
                ahi[mt][1] = prmt_hi(e10, e11); alo[mt][1] = prmt_lo(e10, e11);
                ahi[mt][2] = prmt_hi(e02, e03); alo[mt][2] = prmt_lo(e02, e03);
                ahi[mt][3] = prmt_hi(e12, e13); alo[mt][3] = prmt_lo(e12, e13);
            }
#pragma unroll
            for (int nt = 0; nt < 8; nt++) {
                int col = nt * 8 + group;
                uint32_t wk0 = Vs[k0 * 68 + col];
                uint32_t wk1 = Vs[(k0 + 1) * 68 + col];
                uint32_t wk8 = Vs[(k0 + 8) * 68 + col];
                uint32_t wk9 = Vs[(k0 + 9) * 68 + col];
                uint32_t bhi[2] = { prmt_hi(wk0, wk1), prmt_hi(wk8, wk9) };
                uint32_t blo[2] = { prmt_lo(wk0, wk1), prmt_lo(wk8, wk9) };
#pragma unroll
                for (int mt = 0; mt < 2; mt++) {
                    mma_bf16(acc[mt][nt], ahi[mt], bhi);
                    mma_bf16(acc[mt][nt], ahi[mt], blo);
                    mma_bf16(acc[mt][nt], alo[mt], bhi);
                }
            }
        }
        __syncthreads();
    }

#pragma unroll
    for (int mt = 0; mt < 2; mt++) {
        int mr = m0 + mt * 16 + group;
#pragma unroll
        for (int nt = 0; nt < 8; nt++) {
            int col = nt * 8 + cc * 2;
            atomicAdd(&g_kvs[(bh * 256 + mr) * 64 + col],         acc[mt][nt][0]);
            atomicAdd(&g_kvs[(bh * 256 + mr) * 64 + col + 1],     acc[mt][nt][1]);
            atomicAdd(&g_kvs[(bh * 256 + mr + 8) * 64 + col],     acc[mt][nt][2]);
            atomicAdd(&g_kvs[(bh * 256 + mr + 8) * 64 + col + 1], acc[mt][nt][3]);
        }
    }
}

// ---------------------------------------------------------------------------
// av (tensor): av[g, h*64+d] = norms[g,h] * sum_m q'[g,h,m] * kvs[bh,m,d]
// 256 threads / 8 warps (4x2), warp tile 32g x 32d, 2 CTAs/SM.
// ---------------------------------------------------------------------------
__global__ __launch_bounds__(256, 2) void av_tc(const float* __restrict__ qp)
{
    __shared__ uint32_t As[128 * AS_STRIDE];  // [g(128)][k(32)] packed
    __shared__ uint32_t Bs[32 * 68];          // [k(32)][d(64)] packed

    int h  = blockIdx.y;
    int g0 = blockIdx.x * 128;
    int bh = (g0 >> 12) * Hn + h;
    int tid = threadIdx.x;
    int wid = tid >> 5, lane = tid & 31;
    int wm = wid >> 1, wn = wid & 1;          // 4 x 2
    int group = lane >> 2, cc = lane & 3;

    float acc[2][4][4];
#pragma unroll
    for (int a = 0; a < 2; a++)
#pragma unroll
        for (int c = 0; c < 4; c++)
#pragma unroll
            for (int e = 0; e < 4; e++) acc[a][c][e] = 0.f;

    for (int mc = 0; mc < 256; mc += 32) {
        // A: q' 128 g x 32 k
#pragma unroll
        for (int i = 0; i < 4; i++) {
            int m = (tid >> 3) + i * 32;
            float4 f = *(const float4*)&qp[((size_t)(g0 + m) * Hn + h) * 256 + mc + (tid & 7) * 4];
            uint4 u;
            u.x = pack_bf16_hl(f.x); u.y = pack_bf16_hl(f.y);
            u.z = pack_bf16_hl(f.z); u.w = pack_bf16_hl(f.w);
            *(uint4*)&As[m * AS_STRIDE + (tid & 7) * 4] = u;
        }
        // B: kvs 32 k x 64 d
#pragma unroll
        for (int i = 0; i < 2; i++) {
            int v = tid + i * 256;
            int kk = v >> 4, dq = v & 15;
            float4 f = *(const float4*)&g_kvs[(size_t)(bh * 256 + mc + kk) * 64 + dq * 4];
            uint4 u;
            u.x = pack_bf16_hl(f.x); u.y = pack_bf16_hl(f.y);
            u.z = pack_bf16_hl(f.z); u.w = pack_bf16_hl(f.w);
            *(uint4*)&Bs[kk * 68 + dq * 4] = u;
        }
        __syncthreads();

#pragma unroll
        for (int ks = 0; ks < 32; ks += 16) {
            uint32_t ahi[2][4], alo[2][4];
#pragma unroll
            for (int mt = 0; mt < 2; mt++) {
                int r0  = wm * 32 + mt * 16 + group;
                int kw0 = ks + cc * 2;
                int kw1 = kw0 + 8;
                uint2 w00 = *(uint2*)&As[r0 * AS_STRIDE + kw0];
                uint2 w10 = *(uint2*)&As[(r0 + 8) * AS_STRIDE + kw0];
                uint2 w01 = *(uint2*)&As[r0 * AS_STRIDE + kw1];
                uint2 w11 = *(uint2*)&As[(r0 + 8) * AS_STRIDE + kw1];
                ahi[mt][0] = prmt_hi(w00.x, w00.y); alo[mt][0] = prmt_lo(w00.x, w00.y);
                ahi[mt][1] = prmt_hi(w10.x, w10.y); alo[mt][1] = prmt_lo(w10.x, w10.y);
                ahi[mt][2] = prmt_hi(w01.x, w01.y); alo[mt][2] = prmt_lo(w01.x, w01.y);
                ahi[mt][3] = prmt_hi(w11.x, w11.y); alo[mt][3] = prmt_lo(w11.x, w11.y);
            }
#pragma unroll
            for (int nt = 0; nt < 4; nt++) {
                int col = wn * 32 + nt * 8 + group;
                int kr  = ks + cc * 2;
                uint32_t wk0 = Bs[kr * 68 + col];
                uint32_t wk1 = Bs[(kr + 1) * 68 + col];
                uint32_t wk8 = Bs[(kr + 8) * 68 + col];
                uint32_t wk9 = Bs[(kr + 9) * 68 + col];
                uint32_t bhi[2] = { prmt_hi(wk0, wk1), prmt_hi(wk8, wk9) };
                uint32_t blo[2] = { prmt_lo(wk0, wk1), prmt_lo(wk8, wk9) };
#pragma unroll
                for (int mt = 0; mt < 2; mt++) {
                    mma_bf16(acc[mt][nt], ahi[mt], bhi);
                    mma_bf16(acc[mt][nt], ahi[mt], blo);
                    mma_bf16(acc[mt][nt], alo[mt], bhi);
                }
            }
        }
        __syncthreads();
    }

#pragma unroll
    for (int mt = 0; mt < 2; mt++) {
        int g  = g0 + wm * 32 + mt * 16 + group;
        float nr0 = g_norms[(size_t)g * Hn + h];
        float nr1 = g_norms[(size_t)(g + 8) * Hn + h];
#pragma unroll
        for (int nt = 0; nt < 4; nt++) {
            int c = h * 64 + wn * 32 + nt * 8 + cc * 2;
            *(float2*)&g_av[(size_t)g * Dn + c]
                = make_float2(nr0 * acc[mt][nt][0], nr0 * acc[mt][nt][1]);
            *(float2*)&g_av[(size_t)(g + 8) * Dn + c]
                = make_float2(nr1 * acc[mt][nt][2], nr1 * acc[mt][nt][3]);
        }
    }
}

// ---------------------------------------------------------------------------
// Launch
// ---------------------------------------------------------------------------
extern "C" void kernel_launch(void* const* d_in, const int* in_sizes, int n_in,
                              void* d_out, int out_size)
{
    const float* src   = (const float*)d_in[0];   // source_input [B,N,D]
    const float* posf  = (const float*)d_in[1];   // pos_ft
    const float* slope = (const float*)d_in[2];   // pos_ft_slopes
    const float* Wv    = (const float*)d_in[3];   // value_weight [D,H,DH]
    const float* Wp    = (const float*)d_in[4];   // pos_ft_weight
    const float* scale = (const float*)d_in[5];   // [H]
    const float* offs  = (const float*)d_in[6];   // [H]
    const float* Wout  = (const float*)d_in[7];   // [H*DH, D]
    const float* proj  = (const float*)d_in[8];   // [M, DH]
    float* out = (float*)d_out;

    // Output layout: [out (B*N*D) | q_prime (B*N*H*2M) | k_prime (B*N*H*2M)]
    const long QOFF = (long)GTOT * Dn;                 //  8,388,608
    const long KOFF = QOFF + (long)GTOT * Hn * 2 * Mn; // 41,943,040
    const long TOT  = KOFF + (long)GTOT * Hn * 2 * Mn; // 75,497,472

    float *qp, *kp;
    if ((long)out_size >= TOT) {
        qp = out + QOFF;
        kp = out + KOFF;
    } else {
        cudaGetSymbolAddress((void**)&qp, g_qp);
        cudaGetSymbolAddress((void**)&kp, g_kp);
    }

    size_t fsmem = (size_t)(64*132 + 2*64*68) * sizeof(float);  // 69632 B
    cudaFuncSetAttribute(fourier_k, cudaFuncAttributeMaxDynamicSharedMemorySize,
                         (int)fsmem);

    zero_kvs_k<<<2048, 256>>>();
    tc_proj<<<dim3(128, 4, 3), 256>>>(src, posf, slope, Wv, Wp);
    fourier_k<<<dim3(256, 8), 256, fsmem>>>(scale, offs, proj, qp, kp);
    kvs_tc<<<dim3(32, 16), 256>>>(kp);
    av_tc<<<dim3(128, 8), 256>>>(qp);
    tc_final<<<dim3(128, 4), 256>>>(Wout, out);
}